// round 2
// baseline (speedup 1.0000x reference)
#include <cuda_runtime.h>

#define NAB 10
#define MAXN 131072

static __device__ int g_cnt[NAB];
static __device__ int g_off[NAB+1];
static __device__ int g_cursor[NAB];
static __device__ int g_tb_s[NAB+1];
static __device__ int g_tb_v[NAB+1];
static __device__ int g_zn[MAXN];
static __device__ int g_perm[MAXN];
static __device__ float g_W[20*256*128];

__device__ __forceinline__ float tf32r(float x){
  unsigned u; asm("cvt.rna.tf32.f32 %0, %1;" : "=r"(u) : "f"(x));
  return __uint_as_float(u);
}

__device__ __forceinline__ void mma_tf32(float c[4],
    unsigned a0, unsigned a1, unsigned a2, unsigned a3,
    unsigned b0, unsigned b1){
  asm volatile("mma.sync.aligned.m16n8k8.row.col.f32.tf32.tf32.f32 "
    "{%0,%1,%2,%3}, {%4,%5,%6,%7}, {%8,%9}, {%0,%1,%2,%3};"
    : "+f"(c[0]), "+f"(c[1]), "+f"(c[2]), "+f"(c[3])
    : "r"(a0), "r"(a1), "r"(a2), "r"(a3), "r"(b0), "r"(b1));
}

__global__ void k_prepw(const float* __restrict__ Wl0, const float* __restrict__ Wl1,
                        const float* __restrict__ Wt0, const float* __restrict__ Wt1){
  int idx = blockIdx.x*blockDim.x + threadIdx.x;
  if (idx >= 20*32768) return;
  int m = idx >> 15;            // 0..19 = type*10 + a
  int r = idx & 32767;
  int k = r >> 7, o = r & 127;
  int type = m / 10, a = m - type*10;
  float v;
  if (k < 128) {
    const float* W = type ? Wl1 : Wl0;
    v = W[k*128 + o] * 0.08838834764831845f;          // 1/sqrt(128)
  } else {
    const float* W = type ? Wt1 : Wt0;
    v = W[(k-128)*1280 + a*128 + o] * 0.027950849718747373f; // 1/sqrt(1280)
  }
  g_W[idx] = tf32r(v);
}

__global__ void k_zero(){ if (threadIdx.x < NAB) g_cnt[threadIdx.x] = 0; }

__global__ void k_hist(const float* __restrict__ attrs, int N){
  __shared__ int s[NAB];
  if (threadIdx.x < NAB) s[threadIdx.x] = 0;
  __syncthreads();
  int n = blockIdx.x*blockDim.x + threadIdx.x;
  if (n < N){
    const float* p = attrs + (size_t)n*NAB;
    int a = 0; float best = p[0];
    #pragma unroll
    for (int i=1;i<NAB;++i){ float v=p[i]; if (v>best){best=v;a=i;} }
    g_zn[n] = a;
    atomicAdd(&s[a], 1);
  }
  __syncthreads();
  if (threadIdx.x < NAB) atomicAdd(&g_cnt[threadIdx.x], s[threadIdx.x]);
}

__global__ void k_scan(){
  if (threadIdx.x == 0 && blockIdx.x == 0){
    g_off[0]=0; g_tb_s[0]=0; g_tb_v[0]=0;
    for (int a=0;a<NAB;++a){
      int c = g_cnt[a];
      g_off[a+1]  = g_off[a] + c;
      g_cursor[a] = g_off[a];
      g_tb_s[a+1] = g_tb_s[a] + (c + 127)/128;
      g_tb_v[a+1] = g_tb_v[a] + (c + 41)/42;
    }
  }
}

__global__ void k_scatter(int N){
  __shared__ int sc[NAB], sb[NAB];
  if (threadIdx.x < NAB) sc[threadIdx.x] = 0;
  __syncthreads();
  int n = blockIdx.x*blockDim.x + threadIdx.x;
  int a = 0, p = 0;
  bool valid = (n < N);
  if (valid){ a = g_zn[n]; p = atomicAdd(&sc[a], 1); }
  __syncthreads();
  if (threadIdx.x < NAB) sb[threadIdx.x] = atomicAdd(&g_cursor[threadIdx.x], sc[threadIdx.x]);
  __syncthreads();
  if (valid) g_perm[sb[a] + p] = n;
}

// Persistent GEMM: s-tiles (128 nodes x 128 cols, K=256) and v-tiles
// (42 nodes * 3 channels = 126 rows x 128 cols, K=256).
__global__ void __launch_bounds__(256,1) k_main(
    const float* __restrict__ Xm, const float* __restrict__ Xf,
    float* __restrict__ out){
  extern __shared__ float smf[];
  float* Ws = smf;              // [256][132]
  float* As = smf + 256*132;    // [128][68], reused for C staging
  __shared__ int s_nodes[128];

  const int tid  = threadIdx.x;
  const int lane = tid & 31;
  const int warp = tid >> 5;
  const int g4 = lane >> 2, t4 = lane & 3;
  const int wm = warp & 3, wn = warp >> 2;   // 4x2 warp grid, 32x64 each

  const int ts_tot = g_tb_s[NAB];
  const int tv_tot = g_tb_v[NAB];
  const int total  = ts_tot + tv_tot;
  const int per = (total + gridDim.x - 1)/gridDim.x;
  int t0 = blockIdx.x * per;
  int t1 = t0 + per; if (t1 > total) t1 = total;
  int cur = -1;

  for (int t = t0; t < t1; ++t){
    const bool isv = (t >= ts_tot);
    const int tt = isv ? t - ts_tot : t;
    const int* tb = isv ? g_tb_v : g_tb_s;
    int a = 0;
    while (tt >= tb[a+1]) ++a;
    const int tile  = tt - tb[a];
    const int width = isv ? 42 : 128;
    const int base  = g_off[a] + tile*width;
    const int end   = g_off[a+1];

    __syncthreads();  // previous tile fully done with Ws/As/s_nodes

    const int key = (isv ? NAB : 0) + a;
    if (key != cur){
      cur = key;
      const float4* src = (const float4*)(g_W + key*32768);
      #pragma unroll 8
      for (int q = tid; q < 8192; q += 256){
        int k = q >> 5, o4 = (q & 31) << 2;
        *(float4*)(Ws + k*132 + o4) = src[q];
      }
    }
    if (tid < width)
      s_nodes[tid] = (base + tid < end) ? g_perm[base + tid] : -1;

    float acc[2][8][4];
    #pragma unroll
    for (int i=0;i<2;++i)
      #pragma unroll
      for (int j=0;j<8;++j)
        #pragma unroll
        for (int e=0;e<4;++e) acc[i][j][e] = 0.f;

    for (int kc = 0; kc < 4; ++kc){
      __syncthreads();  // Ws/s_nodes ready; prior chunk MMA done before overwriting As
      const float* src = (kc < 2) ? Xm : Xf;
      if (!isv){
        const int cb = (kc & 1)*64;
        #pragma unroll 2
        for (int q = tid; q < 2048; q += 256){
          int ln = q >> 4, u = (q & 15) << 2;
          int node = s_nodes[ln];
          float4 v = make_float4(0.f,0.f,0.f,0.f);
          if (node >= 0) v = *(const float4*)(src + (size_t)node*512 + cb + u);
          float* d = As + ln*68 + u;
          d[0]=tf32r(v.x); d[1]=tf32r(v.y); d[2]=tf32r(v.z); d[3]=tf32r(v.w);
        }
      } else {
        const int cb = 128 + (kc & 1)*192;
        #pragma unroll 2
        for (int q = tid; q < 42*48; q += 256){
          int ln = q / 48, u = (q - ln*48) << 2;
          int node = s_nodes[ln];
          float4 v = make_float4(0.f,0.f,0.f,0.f);
          if (node >= 0) v = *(const float4*)(src + (size_t)node*512 + cb + u);
          float vv[4] = {v.x, v.y, v.z, v.w};
          #pragma unroll
          for (int e=0;e<4;++e){
            int jr = u + e;
            int il = jr/3, x = jr - 3*il;     // src col = 128 + 3*i + x
            As[(3*ln + x)*68 + il] = tf32r(vv[e]);
          }
        }
      }
      __syncthreads();

      #pragma unroll
      for (int kk = 0; kk < 64; kk += 8){
        unsigned b0[8], b1[8];
        const float* Wk = Ws + (kc*64 + kk + t4)*132 + wn*64 + g4;
        #pragma unroll
        for (int ni=0; ni<8; ++ni){
          b0[ni] = __float_as_uint(Wk[ni*8]);
          b1[ni] = __float_as_uint(Wk[4*132 + ni*8]);
        }
        #pragma unroll
        for (int mi=0; mi<2; ++mi){
          const float* Ar = As + (wm*32 + mi*16 + g4)*68 + kk + t4;
          unsigned a0 = __float_as_uint(Ar[0]);
          unsigned a1 = __float_as_uint(Ar[8*68]);
          unsigned a2 = __float_as_uint(Ar[4]);
          unsigned a3 = __float_as_uint(Ar[8*68 + 4]);
          #pragma unroll
          for (int ni=0; ni<8; ++ni)
            mma_tf32(acc[mi][ni], a0,a1,a2,a3, b0[ni], b1[ni]);
        }
      }
    }

    // stage C through As in two 64-col passes, then coalesced global stores
    for (int p = 0; p < 2; ++p){
      __syncthreads();  // As free (last MMA done / previous pass reads done)
      if (wn == p){
        #pragma unroll
        for (int mi=0; mi<2; ++mi){
          int r = wm*32 + mi*16 + g4;
          #pragma unroll
          for (int ni=0; ni<8; ++ni){
            float* d1 = As + r*68 + ni*8 + 2*t4;
            d1[0] = acc[mi][ni][0]; d1[1] = acc[mi][ni][1];
            float* d2 = As + (r+8)*68 + ni*8 + 2*t4;
            d2[0] = acc[mi][ni][2]; d2[1] = acc[mi][ni][3];
          }
        }
      }
      __syncthreads();
      if (!isv){
        for (int q = tid; q < 2048; q += 256){
          int ln = q >> 4, u = (q & 15) << 2;
          int node = s_nodes[ln];
          if (node < 0) continue;
          float4 v = *(float4*)(As + ln*68 + u);
          *(float4*)(out + (size_t)node*512 + p*64 + u) = v;
        }
      } else {
        for (int q = tid; q < 42*48; q += 256){
          int ln = q / 48, u = (q - ln*48) << 2;
          int node = s_nodes[ln];
          if (node < 0) continue;
          float4 v;
          float* vp = (float*)&v;
          #pragma unroll
          for (int e=0;e<4;++e){
            int jr = u + e;
            int ol = jr/3, x = jr - 3*ol;
            vp[e] = As[(3*ln + x)*68 + ol];
          }
          *(float4*)(out + (size_t)node*512 + 128 + p*192 + u) = v;
        }
      }
    }
  }
}

extern "C" void kernel_launch(void* const* d_in, const int* in_sizes, int n_in,
                              void* d_out, int out_size){
  const float* m_i   = (const float*)d_in[0];
  const float* nfeat = (const float*)d_in[1];
  const float* attrs = (const float*)d_in[2];
  const float* Wl0   = (const float*)d_in[3];
  const float* Wl1   = (const float*)d_in[4];
  const float* Wt0   = (const float*)d_in[5];
  const float* Wt1   = (const float*)d_in[6];
  float* out = (float*)d_out;
  int N = in_sizes[0] / 512;
  if (N > MAXN) return;

  cudaFuncSetAttribute(k_main, cudaFuncAttributeMaxDynamicSharedMemorySize, 176128);

  k_prepw<<<(20*32768 + 255)/256, 256>>>(Wl0, Wl1, Wt0, Wt1);
  k_zero<<<1, 32>>>();
  k_hist<<<(N + 255)/256, 256>>>(attrs, N);
  k_scan<<<1, 1>>>();
  k_scatter<<<(N + 255)/256, 256>>>(N);
  k_main<<<148, 256, (256*132 + 128*68)*4>>>(m_i, nfeat, out);
}

// round 4
// speedup vs baseline: 1.7599x; 1.7599x over previous
#include <cuda_runtime.h>
#include <cuda_fp16.h>

#define NAB 10
#define MAXN 131072

static __device__ int g_cnt[NAB];
static __device__ int g_off[NAB+1];
static __device__ int g_cursor[NAB];
static __device__ int g_tb_s[NAB+1];
static __device__ int g_tb_v[NAB+1];
static __device__ int g_zn[MAXN];
static __device__ int g_perm[MAXN];
// fp16 weights: [20 mats][4 k-chunks][128 o][72 k-pad]  (row stride 144B)
static __device__ __half g_Wh[20*4*128*72];

__device__ __forceinline__ unsigned su32(const void* p){
  return (unsigned)__cvta_generic_to_shared(p);
}
__device__ __forceinline__ void ldsm4(unsigned r[4], unsigned addr){
  asm volatile("ldmatrix.sync.aligned.m8n8.x4.shared.b16 {%0,%1,%2,%3}, [%4];"
    : "=r"(r[0]),"=r"(r[1]),"=r"(r[2]),"=r"(r[3]) : "r"(addr));
}
__device__ __forceinline__ void hmma(float c[4], const unsigned a[4],
                                     unsigned b0, unsigned b1){
  asm volatile("mma.sync.aligned.m16n8k16.row.col.f32.f16.f16.f32 "
    "{%0,%1,%2,%3},{%4,%5,%6,%7},{%8,%9},{%0,%1,%2,%3};"
    : "+f"(c[0]),"+f"(c[1]),"+f"(c[2]),"+f"(c[3])
    : "r"(a[0]),"r"(a[1]),"r"(a[2]),"r"(a[3]),"r"(b0),"r"(b1));
}

// ---------- setup kernels ----------
__global__ void k_prepw(const float* __restrict__ Wl0, const float* __restrict__ Wl1,
                        const float* __restrict__ Wt0, const float* __restrict__ Wt1){
  int idx = blockIdx.x*blockDim.x + threadIdx.x;
  if (idx >= 20*32768) return;
  int mat = idx >> 15;
  int r = idx & 32767;
  int k = r >> 7, o = r & 127;
  int type = mat / 10, a = mat - type*10;
  float v;
  if (k < 128) {
    const float* W = type ? Wl1 : Wl0;
    v = W[k*128 + o] * 0.08838834764831845f;                 // LIN: 1/sqrt(128)
  } else {
    const float* W = type ? Wt1 : Wt0;
    v = W[(k-128)*1280 + a*128 + o] * 0.027950849718747373f; // TP: 1/sqrt(1280)
  }
  int kc = k >> 6, kk = k & 63;
  g_Wh[(size_t)mat*36864 + kc*9216 + o*72 + kk] = __float2half_rn(v);
}

__global__ void k_padw(){   // zero the 8-half pad of every row so ldmatrix reads are clean
  int idx = blockIdx.x*blockDim.x + threadIdx.x;
  if (idx >= 20*4*128*8) return;
  int row = idx >> 3, e = idx & 7;
  g_Wh[(size_t)row*72 + 64 + e] = __float2half_rn(0.f);
}

__global__ void k_zero(){ if (threadIdx.x < NAB) g_cnt[threadIdx.x] = 0; }

__global__ void k_hist(const float* __restrict__ attrs, int N){
  __shared__ int s[NAB];
  if (threadIdx.x < NAB) s[threadIdx.x] = 0;
  __syncthreads();
  int n = blockIdx.x*blockDim.x + threadIdx.x;
  if (n < N){
    const float* p = attrs + (size_t)n*NAB;
    int a = 0; float best = p[0];
    #pragma unroll
    for (int i=1;i<NAB;++i){ float v=p[i]; if (v>best){best=v;a=i;} }
    g_zn[n] = a;
    atomicAdd(&s[a], 1);
  }
  __syncthreads();
  if (threadIdx.x < NAB) atomicAdd(&g_cnt[threadIdx.x], s[threadIdx.x]);
}

__global__ void k_scan(){
  if (threadIdx.x == 0 && blockIdx.x == 0){
    g_off[0]=0; g_tb_s[0]=0; g_tb_v[0]=0;
    for (int a=0;a<NAB;++a){
      int c = g_cnt[a];
      g_off[a+1]  = g_off[a] + c;
      g_cursor[a] = g_off[a];
      g_tb_s[a+1] = g_tb_s[a] + (c + 127)/128;
      g_tb_v[a+1] = g_tb_v[a] + (c + 41)/42;
    }
  }
}

__global__ void k_scatter(int N){
  __shared__ int sc[NAB], sb[NAB];
  if (threadIdx.x < NAB) sc[threadIdx.x] = 0;
  __syncthreads();
  int n = blockIdx.x*blockDim.x + threadIdx.x;
  int a = 0, p = 0;
  bool valid = (n < N);
  if (valid){ a = g_zn[n]; p = atomicAdd(&sc[a], 1); }
  __syncthreads();
  if (threadIdx.x < NAB) sb[threadIdx.x] = atomicAdd(&g_cursor[threadIdx.x], sc[threadIdx.x]);
  __syncthreads();
  if (valid) g_perm[sb[a] + p] = n;
}

// ---------- main kernel ----------
// SMEM: [0, 73728)        B weights: 4 chunks x [128 o][72 halves] (144B rows)
//       [73728, 73728+34816) A buffer [128 m][72 halves] (18432B) / C stage [128][68] f32
#define B_BYTES 73728
#define SMEM_BYTES (B_BYTES + 34816)

__global__ void __launch_bounds__(256) k_main(
    const float* __restrict__ Xm, const float* __restrict__ Xf,
    float* __restrict__ out){
  extern __shared__ char smem[];
  char*  Abuf  = smem + B_BYTES;
  float* stage = (float*)(smem + B_BYTES);
  __shared__ int s_nodes[128];

  const int tid  = threadIdx.x;
  const int lane = tid & 31;
  const int wid  = tid >> 5;
  const int wm = wid & 3, wn = wid >> 2;     // 4x2 warps, each 32 rows x 64 cols
  const int g4 = lane >> 2, t4 = lane & 3;
  const unsigned smb = su32(smem);
  const unsigned Ab  = smb + B_BYTES;

  // ldmatrix per-lane offsets
  const int ra  = lane & 15;                       // A row within 16
  const int ca  = (lane >> 4) << 3;                // A col +0/+8
  const int rb  = ((lane >> 4) & 1)*8 + (lane & 7);// B row within 16
  const int cb2 = ((lane >> 3) & 1) << 3;          // B col +0/+8

  const int ts_tot = g_tb_s[NAB];
  const int tv_tot = g_tb_v[NAB];
  const int total  = ts_tot + tv_tot;
  const int per = (total + gridDim.x - 1)/gridDim.x;
  int t0 = blockIdx.x * per;
  int t1 = t0 + per; if (t1 > total) t1 = total;
  int cur = -1;

  for (int t = t0; t < t1; ++t){
    const bool isv = (t >= ts_tot);
    const int tt = isv ? t - ts_tot : t;
    const int* tb = isv ? g_tb_v : g_tb_s;
    int a = 0;
    while (tt >= tb[a+1]) ++a;
    const int tile  = tt - tb[a];
    const int width = isv ? 42 : 128;
    const int base  = g_off[a] + tile*width;
    const int end   = g_off[a+1];

    if (tid < width)
      s_nodes[tid] = (base + tid < end) ? g_perm[base + tid] : -1;

    const int key = (isv ? NAB : 0) + a;
    if (key != cur){
      cur = key;
      const float4* srcW = (const float4*)(g_Wh + (size_t)key*36864);
      float4* dstW = (float4*)smem;
      #pragma unroll 6
      for (int q = tid; q < 4608; q += 256) dstW[q] = srcW[q];
    }
    __syncthreads();   // s_nodes + B ready; prev tile readers done

    float acc[2][8][4];
    #pragma unroll
    for (int i=0;i<2;++i)
      #pragma unroll
      for (int j=0;j<8;++j)
        #pragma unroll
        for (int e=0;e<4;++e) acc[i][j][e] = 0.f;

    for (int kc = 0; kc < 4; ++kc){
      const float* src = (kc < 2) ? Xm : Xf;
      // ---- gather A chunk (64 k) into fp16 SMEM ----
      if (!isv){
        const int cb = (kc & 1)*64;
        #pragma unroll 2
        for (int q = tid; q < 2048; q += 256){
          int ln = q >> 4, u = (q & 15) << 2;
          int node = s_nodes[ln];
          if (node < 0) continue;
          float4 v = *(const float4*)(src + (size_t)node*512 + cb + u);
          __half2* d = (__half2*)(Abuf + ln*144 + u*2);
          d[0] = __floats2half2_rn(v.x, v.y);
          d[1] = __floats2half2_rn(v.z, v.w);
        }
      } else {
        const int cb = 128 + (kc & 1)*192;
        #pragma unroll 2
        for (int q = tid; q < 2016; q += 256){
          int ln = q / 48, u = (q - ln*48) << 2;
          int node = s_nodes[ln];
          if (node < 0) continue;
          float4 v = *(const float4*)(src + (size_t)node*512 + cb + u);
          float vv[4] = {v.x, v.y, v.z, v.w};
          #pragma unroll
          for (int e=0;e<4;++e){
            int jr = u + e;
            int il = jr/3, x = jr - 3*il;
            *(__half*)(Abuf + (3*ln + x)*144 + il*2) = __float2half_rn(vv[e]);
          }
        }
      }
      __syncthreads();

      // ---- MMA: 4 x k16 steps, fp16 HMMA via ldmatrix ----
      const unsigned Bk = smb + (unsigned)(kc*18432);
      #pragma unroll
      for (int ks = 0; ks < 4; ++ks){
        const int k0 = ks*16;
        unsigned af[2][4];
        ldsm4(af[0], Ab + (unsigned)((wm*32      + ra)*144 + (k0+ca)*2));
        ldsm4(af[1], Ab + (unsigned)((wm*32 + 16 + ra)*144 + (k0+ca)*2));
        #pragma unroll
        for (int j = 0; j < 4; ++j){
          unsigned bf[4];
          ldsm4(bf, Bk + (unsigned)((wn*64 + j*16 + rb)*144 + (k0+cb2)*2));
          #pragma unroll
          for (int mi = 0; mi < 2; ++mi){
            hmma(acc[mi][2*j  ], af[mi], bf[0], bf[1]);
            hmma(acc[mi][2*j+1], af[mi], bf[2], bf[3]);
          }
        }
      }
      __syncthreads();  // MMA done before next gather overwrites Abuf
    }

    // ---- epilogue: two 64-col passes, regs -> stage -> global ----
    for (int p = 0; p < 2; ++p){
      if (wn == p){
        #pragma unroll
        for (int mi=0; mi<2; ++mi){
          int r = wm*32 + mi*16 + g4;
          #pragma unroll
          for (int ni=0; ni<8; ++ni){
            float* d1 = stage + r*68 + ni*8 + 2*t4;
            d1[0] = acc[mi][ni][0]; d1[1] = acc[mi][ni][1];
            float* d2 = stage + (r+8)*68 + ni*8 + 2*t4;
            d2[0] = acc[mi][ni][2]; d2[1] = acc[mi][ni][3];
          }
        }
      }
      __syncthreads();
      if (!isv){
        for (int q = tid; q < 2048; q += 256){
          int ln = q >> 4, u = (q & 15) << 2;
          int node = s_nodes[ln];
          if (node < 0) continue;
          float4 v = *(float4*)(stage + ln*68 + u);
          *(float4*)(out + (size_t)node*512 + p*64 + u) = v;
        }
      } else {
        for (int q = tid; q < 2016; q += 256){
          int ln = q / 48, u = (q - ln*48) << 2;
          int node = s_nodes[ln];
          if (node < 0) continue;
          float4 v;
          float* vp = (float*)&v;
          #pragma unroll
          for (int e=0;e<4;++e){
            int jr = u + e;
            int ol = jr/3, x = jr - 3*ol;
            vp[e] = stage[(3*ln + x)*68 + ol];
          }
          *(float4*)(out + (size_t)node*512 + 128 + p*192 + u) = v;
        }
      }
      __syncthreads();
    }
  }
}

extern "C" void kernel_launch(void* const* d_in, const int* in_sizes, int n_in,
                              void* d_out, int out_size){
  const float* m_i   = (const float*)d_in[0];
  const float* nfeat = (const float*)d_in[1];
  const float* attrs = (const float*)d_in[2];
  const float* Wl0   = (const float*)d_in[3];
  const float* Wl1   = (const float*)d_in[4];
  const float* Wt0   = (const float*)d_in[5];
  const float* Wt1   = (const float*)d_in[6];
  float* out = (float*)d_out;
  int N = in_sizes[0] / 512;
  if (N > MAXN) return;

  cudaFuncSetAttribute(k_main, cudaFuncAttributeMaxDynamicSharedMemorySize, SMEM_BYTES);

  k_prepw<<<(20*32768 + 255)/256, 256>>>(Wl0, Wl1, Wt0, Wt1);
  k_padw<<<(20*4*128*8 + 255)/256, 256>>>();
  k_zero<<<1, 32>>>();
  k_hist<<<(N + 255)/256, 256>>>(attrs, N);
  k_scan<<<1, 1>>>();
  k_scatter<<<(N + 255)/256, 256>>>(N);
  k_main<<<296, 256, SMEM_BYTES>>>(m_i, nfeat, out);
}

// round 5
// speedup vs baseline: 2.4305x; 1.3811x over previous
#include <cuda_runtime.h>
#include <cuda_fp16.h>

#define NAB 10
#define MAXN 131072

static __device__ int g_cnt[NAB];
static __device__ int g_off[NAB+1];
static __device__ int g_cursor[NAB];
static __device__ int g_tb_s[NAB+1];
static __device__ int g_tb_v[NAB+1];
static __device__ int g_zn[MAXN];
static __device__ int g_perm[MAXN];
// fp16 weights: [20 mats][4 k-chunks][128 o][72 k-pad] (144B rows; pad stays 0)
static __device__ __half g_Wh[20*4*128*72];

__device__ __forceinline__ unsigned su32(const void* p){
  return (unsigned)__cvta_generic_to_shared(p);
}
__device__ __forceinline__ void ldsm4(unsigned r[4], unsigned addr){
  asm volatile("ldmatrix.sync.aligned.m8n8.x4.shared.b16 {%0,%1,%2,%3}, [%4];"
    : "=r"(r[0]),"=r"(r[1]),"=r"(r[2]),"=r"(r[3]) : "r"(addr));
}
__device__ __forceinline__ void hmma(float c[4], const unsigned a[4],
                                     unsigned b0, unsigned b1){
  asm volatile("mma.sync.aligned.m16n8k16.row.col.f32.f16.f16.f32 "
    "{%0,%1,%2,%3},{%4,%5,%6,%7},{%8,%9},{%0,%1,%2,%3};"
    : "+f"(c[0]),"+f"(c[1]),"+f"(c[2]),"+f"(c[3])
    : "r"(a[0]),"r"(a[1]),"r"(a[2]),"r"(a[3]),"r"(b0),"r"(b1));
}

// ---------- setup kernels ----------
__global__ void k_prepw(const float* __restrict__ Wl0, const float* __restrict__ Wl1,
                        const float* __restrict__ Wt0, const float* __restrict__ Wt1){
  int idx = blockIdx.x*blockDim.x + threadIdx.x;
  if (idx >= 20*32768) return;
  int mat = idx >> 15;
  int r = idx & 32767;
  int k = r >> 7, o = r & 127;
  int type = mat / 10, a = mat - type*10;
  float v;
  if (k < 128) {
    const float* W = type ? Wl1 : Wl0;
    v = W[k*128 + o] * 0.08838834764831845f;                 // LIN: 1/sqrt(128)
  } else {
    const float* W = type ? Wt1 : Wt0;
    v = W[(k-128)*1280 + a*128 + o] * 0.027950849718747373f; // TP: 1/sqrt(1280)
  }
  int kc = k >> 6, kk = k & 63;
  g_Wh[(size_t)mat*36864 + kc*9216 + o*72 + kk] = __float2half_rn(v);
}

__global__ void k_zero(){ if (threadIdx.x < NAB) g_cnt[threadIdx.x] = 0; }

__global__ void k_hist(const float* __restrict__ attrs, int N){
  __shared__ int s[NAB];
  if (threadIdx.x < NAB) s[threadIdx.x] = 0;
  __syncthreads();
  int n = blockIdx.x*blockDim.x + threadIdx.x;
  if (n < N){
    const float* p = attrs + (size_t)n*NAB;
    int a = 0; float best = p[0];
    #pragma unroll
    for (int i=1;i<NAB;++i){ float v=p[i]; if (v>best){best=v;a=i;} }
    g_zn[n] = a;
    atomicAdd(&s[a], 1);
  }
  __syncthreads();
  if (threadIdx.x < NAB) atomicAdd(&g_cnt[threadIdx.x], s[threadIdx.x]);
}

__global__ void k_scan(){
  if (threadIdx.x == 0 && blockIdx.x == 0){
    g_off[0]=0; g_tb_s[0]=0; g_tb_v[0]=0;
    for (int a=0;a<NAB;++a){
      int c = g_cnt[a];
      g_off[a+1]  = g_off[a] + c;
      g_cursor[a] = g_off[a];
      g_tb_s[a+1] = g_tb_s[a] + (c + 127)/128;
      g_tb_v[a+1] = g_tb_v[a] + (c + 41)/42;
    }
  }
}

__global__ void k_scatter(int N){
  __shared__ int sc[NAB], sb[NAB];
  if (threadIdx.x < NAB) sc[threadIdx.x] = 0;
  __syncthreads();
  int n = blockIdx.x*blockDim.x + threadIdx.x;
  int a = 0, p = 0;
  bool valid = (n < N);
  if (valid){ a = g_zn[n]; p = atomicAdd(&sc[a], 1); }
  __syncthreads();
  if (threadIdx.x < NAB) sb[threadIdx.x] = atomicAdd(&g_cursor[threadIdx.x], sc[threadIdx.x]);
  __syncthreads();
  if (valid) g_perm[sb[a] + p] = n;
}

// ---------- main kernel ----------
// SMEM: [0, 73728)            B weights: 4 chunks x [128 o][72 halves] (144B rows)
//       [73728, 73728+36864)  A double buffer: 2 x [128 m][72 halves]
//       [110592, 110592+67584) C stage [128][132] fp32
#define B_BYTES   73728
#define A_BYTES   18432
#define STAGE_OFF (B_BYTES + 2*A_BYTES)
#define SMEM_BYTES (STAGE_OFF + 128*132*4)

__global__ void __launch_bounds__(512) k_main(
    const float* __restrict__ Xm, const float* __restrict__ Xf,
    float* __restrict__ out){
  extern __shared__ char smem[];
  char*  Abuf  = smem + B_BYTES;
  float* stage = (float*)(smem + STAGE_OFF);
  __shared__ int s_nodes[128];

  const int tid  = threadIdx.x;
  const int lane = tid & 31;
  const int wid  = tid >> 5;
  const int wm = wid & 3, wn = wid >> 2;   // 4x4 warps, each 32 rows x 32 cols
  const int g4 = lane >> 2, t4 = lane & 3;
  const unsigned smb = su32(smem);
  const unsigned Ab  = smb + B_BYTES;

  const int ra  = lane & 15;
  const int ca  = (lane >> 4) << 3;
  const int rb  = ((lane >> 4) & 1)*8 + (lane & 7);
  const int cb2 = ((lane >> 3) & 1) << 3;

  const int ts_tot = g_tb_s[NAB];
  const int tv_tot = g_tb_v[NAB];
  const int total  = ts_tot + tv_tot;
  const int per = (total + gridDim.x - 1)/gridDim.x;
  int t0 = blockIdx.x * per;
  int t1 = t0 + per; if (t1 > total) t1 = total;
  int cur = -1;

  for (int t = t0; t < t1; ++t){
    const bool isv = (t >= ts_tot);
    const int tt = isv ? t - ts_tot : t;
    const int* tb = isv ? g_tb_v : g_tb_s;
    int a = 0;
    while (tt >= tb[a+1]) ++a;
    const int tile  = tt - tb[a];
    const int width = isv ? 42 : 128;
    const int base  = g_off[a] + tile*width;
    const int end   = g_off[a+1];

    if (tid < width)
      s_nodes[tid] = (base + tid < end) ? g_perm[base + tid] : -1;

    const int key = (isv ? NAB : 0) + a;
    if (key != cur){
      cur = key;
      const float4* srcW = (const float4*)(g_Wh + (size_t)key*36864);
      float4* dstW = (float4*)smem;
      #pragma unroll 3
      for (int q = tid; q < 4608; q += 512) dstW[q] = srcW[q];
    }
    __syncthreads();   // s_nodes + B ready; prev tile fully done

    // ---- prologue: gather chunk 0 into buf0 ----
    {
      char* Ad = Abuf;
      if (!isv){
        #pragma unroll
        for (int i = 0; i < 4; ++i){
          int q = tid + i*512;
          int ln = q >> 4, u = (q & 15) << 2;
          int node = s_nodes[ln];
          if (node < 0) continue;
          float4 v = *(const float4*)(Xm + (size_t)node*512 + u);
          __half2* d = (__half2*)(Ad + ln*144 + u*2);
          d[0] = __floats2half2_rn(v.x, v.y);
          d[1] = __floats2half2_rn(v.z, v.w);
        }
      } else {
        #pragma unroll
        for (int i = 0; i < 4; ++i){
          int q = tid + i*512;
          if (q >= 2016) break;
          int ln = q / 48, u = (q - ln*48) << 2;
          int node = s_nodes[ln];
          if (node < 0) continue;
          float4 v = *(const float4*)(Xm + (size_t)node*512 + 128 + u);
          float vv[4] = {v.x, v.y, v.z, v.w};
          #pragma unroll
          for (int e=0;e<4;++e){
            int jr = u + e;
            int il = jr/3, x = jr - 3*il;
            *(__half*)(Ad + (3*ln + x)*144 + il*2) = __float2half_rn(vv[e]);
          }
        }
      }
    }

    float acc[2][4][4];
    #pragma unroll
    for (int i=0;i<2;++i)
      #pragma unroll
      for (int j=0;j<4;++j)
        #pragma unroll
        for (int e=0;e<4;++e) acc[i][j][e] = 0.f;

    for (int kc = 0; kc < 4; ++kc){
      __syncthreads();  // chunk kc STS visible; MMA kc-1 done (buffer (kc+1)&1 free)

      // ---- prefetch chunk kc+1 into registers (hides under MMA) ----
      float4 pv[4];
      const int nk = kc + 1;
      if (nk < 4){
        const float* src = (nk < 2) ? Xm : Xf;
        if (!isv){
          const int cb = (nk & 1)*64;
          #pragma unroll
          for (int i = 0; i < 4; ++i){
            int q = tid + i*512;
            int ln = q >> 4, u = (q & 15) << 2;
            int node = s_nodes[ln];
            if (node >= 0) pv[i] = *(const float4*)(src + (size_t)node*512 + cb + u);
          }
        } else {
          const int cb = 128 + (nk & 1)*192;
          #pragma unroll
          for (int i = 0; i < 4; ++i){
            int q = tid + i*512;
            if (q >= 2016) break;
            int ln = q / 48, u = (q - ln*48) << 2;
            int node = s_nodes[ln];
            if (node >= 0) pv[i] = *(const float4*)(src + (size_t)node*512 + cb + u);
          }
        }
      }

      // ---- MMA on chunk kc ----
      const unsigned Ac = Ab + (unsigned)((kc & 1)*A_BYTES);
      const unsigned Bk = smb + (unsigned)(kc*A_BYTES);
      #pragma unroll
      for (int ks = 0; ks < 4; ++ks){
        const int k0 = ks*16;
        unsigned af[2][4], bf[2][4];
        ldsm4(af[0], Ac + (unsigned)((wm*32      + ra)*144 + (k0+ca)*2));
        ldsm4(af[1], Ac + (unsigned)((wm*32 + 16 + ra)*144 + (k0+ca)*2));
        ldsm4(bf[0], Bk + (unsigned)((wn*32      + rb)*144 + (k0+cb2)*2));
        ldsm4(bf[1], Bk + (unsigned)((wn*32 + 16 + rb)*144 + (k0+cb2)*2));
        #pragma unroll
        for (int mi = 0; mi < 2; ++mi){
          hmma(acc[mi][0], af[mi], bf[0][0], bf[0][1]);
          hmma(acc[mi][1], af[mi], bf[0][2], bf[0][3]);
          hmma(acc[mi][2], af[mi], bf[1][0], bf[1][1]);
          hmma(acc[mi][3], af[mi], bf[1][2], bf[1][3]);
        }
      }

      // ---- convert + store chunk kc+1 into the other buffer ----
      if (nk < 4){
        char* Ad = Abuf + (nk & 1)*A_BYTES;
        if (!isv){
          #pragma unroll
          for (int i = 0; i < 4; ++i){
            int q = tid + i*512;
            int ln = q >> 4, u = (q & 15) << 2;
            if (s_nodes[ln] < 0) continue;
            __half2* d = (__half2*)(Ad + ln*144 + u*2);
            d[0] = __floats2half2_rn(pv[i].x, pv[i].y);
            d[1] = __floats2half2_rn(pv[i].z, pv[i].w);
          }
        } else {
          #pragma unroll
          for (int i = 0; i < 4; ++i){
            int q = tid + i*512;
            if (q >= 2016) break;
            int ln = q / 48, u = (q - ln*48) << 2;
            if (s_nodes[ln] < 0) continue;
            float vv[4] = {pv[i].x, pv[i].y, pv[i].z, pv[i].w};
            #pragma unroll
            for (int e=0;e<4;++e){
              int jr = u + e;
              int il = jr/3, x = jr - 3*il;
              *(__half*)(Ad + (3*ln + x)*144 + il*2) = __float2half_rn(vv[e]);
            }
          }
        }
      }
    }
    __syncthreads();  // last MMA done

    // ---- epilogue: regs -> stage (full 128x128) ----
    #pragma unroll
    for (int mi = 0; mi < 2; ++mi){
      int r = wm*32 + mi*16 + g4;
      #pragma unroll
      for (int jj = 0; jj < 4; ++jj){
        int c = wn*32 + jj*8 + 2*t4;
        float* d1 = stage + r*132 + c;
        d1[0] = acc[mi][jj][0]; d1[1] = acc[mi][jj][1];
        float* d2 = stage + (r+8)*132 + c;
        d2[0] = acc[mi][jj][2]; d2[1] = acc[mi][jj][3];
      }
    }
    __syncthreads();

    // ---- stage -> global ----
    if (!isv){
      #pragma unroll
      for (int i = 0; i < 8; ++i){
        int q = tid + i*512;
        int ln = q >> 5, u = (q & 31) << 2;
        int node = s_nodes[ln];
        if (node < 0) continue;
        float4 v = *(float4*)(stage + ln*132 + u);
        *(float4*)(out + (size_t)node*512 + u) = v;
      }
    } else {
      #pragma unroll
      for (int i = 0; i < 8; ++i){
        int q = tid + i*512;
        if (q >= 4032) break;
        int ln = q / 96, u = (q - ln*96) << 2;
        int node = s_nodes[ln];
        if (node < 0) continue;
        float4 v;
        float* vp = (float*)&v;
        #pragma unroll
        for (int e=0;e<4;++e){
          int jr = u + e;
          int ol = jr/3, x = jr - 3*ol;
          vp[e] = stage[(3*ln + x)*132 + ol];
        }
        *(float4*)(out + (size_t)node*512 + 128 + u) = v;
      }
    }
    __syncthreads();  // stores done before next tile rewrites s_nodes/stage
  }
}

extern "C" void kernel_launch(void* const* d_in, const int* in_sizes, int n_in,
                              void* d_out, int out_size){
  const float* m_i   = (const float*)d_in[0];
  const float* nfeat = (const float*)d_in[1];
  const float* attrs = (const float*)d_in[2];
  const float* Wl0   = (const float*)d_in[3];
  const float* Wl1   = (const float*)d_in[4];
  const float* Wt0   = (const float*)d_in[5];
  const float* Wt1   = (const float*)d_in[6];
  float* out = (float*)d_out;
  int N = in_sizes[0] / 512;
  if (N > MAXN) return;

  cudaFuncSetAttribute(k_main, cudaFuncAttributeMaxDynamicSharedMemorySize, SMEM_BYTES);

  k_prepw<<<(20*32768 + 255)/256, 256>>>(Wl0, Wl1, Wt0, Wt1);
  k_zero<<<1, 32>>>();
  k_hist<<<(N + 255)/256, 256>>>(attrs, N);
  k_scan<<<1, 1>>>();
  k_scatter<<<(N + 255)/256, 256>>>(N);
  k_main<<<148, 512, SMEM_BYTES>>>(m_i, nfeat, out);
}

// round 6
// speedup vs baseline: 2.7345x; 1.1251x over previous
#include <cuda_runtime.h>
#include <cuda_fp16.h>

#define NAB 10
#define MAXN 131072
#define CHUNK 4

static __device__ int g_cnt[NAB];
static __device__ int g_off[NAB+1];
static __device__ int g_cursor[NAB];
static __device__ int g_tb_s[NAB+1];
static __device__ int g_tb_v[NAB+1];
static __device__ int g_zn[MAXN];
static __device__ int g_perm[MAXN];
static __device__ int g_work;
// fp16 weights: [20 mats][4 k-chunks][128 o][72 k-pad] (144B rows; pad stays 0)
static __device__ __half g_Wh[20*4*128*72];

__device__ __forceinline__ unsigned su32(const void* p){
  return (unsigned)__cvta_generic_to_shared(p);
}
__device__ __forceinline__ void ldsm4(unsigned r[4], unsigned addr){
  asm volatile("ldmatrix.sync.aligned.m8n8.x4.shared.b16 {%0,%1,%2,%3}, [%4];"
    : "=r"(r[0]),"=r"(r[1]),"=r"(r[2]),"=r"(r[3]) : "r"(addr));
}
__device__ __forceinline__ void hmma(float c[4], const unsigned a[4],
                                     unsigned b0, unsigned b1){
  asm volatile("mma.sync.aligned.m16n8k16.row.col.f32.f16.f16.f32 "
    "{%0,%1,%2,%3},{%4,%5,%6,%7},{%8,%9},{%0,%1,%2,%3};"
    : "+f"(c[0]),"+f"(c[1]),"+f"(c[2]),"+f"(c[3])
    : "r"(a[0]),"r"(a[1]),"r"(a[2]),"r"(a[3]),"r"(b0),"r"(b1));
}

// ---------- setup kernels ----------
__global__ void k_prepw(const float* __restrict__ Wl0, const float* __restrict__ Wl1,
                        const float* __restrict__ Wt0, const float* __restrict__ Wt1){
  int idx = blockIdx.x*blockDim.x + threadIdx.x;
  if (idx >= 20*32768) return;
  int mat = idx >> 15;
  int r = idx & 32767;
  int k = r >> 7, o = r & 127;
  int type = mat / 10, a = mat - type*10;
  float v;
  if (k < 128) {
    const float* W = type ? Wl1 : Wl0;
    v = W[k*128 + o] * 0.08838834764831845f;                 // LIN: 1/sqrt(128)
  } else {
    const float* W = type ? Wt1 : Wt0;
    v = W[(k-128)*1280 + a*128 + o] * 0.027950849718747373f; // TP: 1/sqrt(1280)
  }
  int kc = k >> 6, kk = k & 63;
  g_Wh[(size_t)mat*36864 + kc*9216 + o*72 + kk] = __float2half_rn(v);
}

__global__ void k_zero(){ if (threadIdx.x < NAB) g_cnt[threadIdx.x] = 0; }

__global__ void k_hist(const float* __restrict__ attrs, int N){
  __shared__ int s[NAB];
  if (threadIdx.x < NAB) s[threadIdx.x] = 0;
  __syncthreads();
  int n = blockIdx.x*blockDim.x + threadIdx.x;
  if (n < N){
    const float* p = attrs + (size_t)n*NAB;
    int a = 0; float best = p[0];
    #pragma unroll
    for (int i=1;i<NAB;++i){ float v=p[i]; if (v>best){best=v;a=i;} }
    g_zn[n] = a;
    atomicAdd(&s[a], 1);
  }
  __syncthreads();
  if (threadIdx.x < NAB) atomicAdd(&g_cnt[threadIdx.x], s[threadIdx.x]);
}

__global__ void k_scan(){
  if (threadIdx.x == 0 && blockIdx.x == 0){
    g_work = 0;
    g_off[0]=0; g_tb_s[0]=0; g_tb_v[0]=0;
    for (int a=0;a<NAB;++a){
      int c = g_cnt[a];
      g_off[a+1]  = g_off[a] + c;
      g_cursor[a] = g_off[a];
      g_tb_s[a+1] = g_tb_s[a] + (c + 127)/128;
      g_tb_v[a+1] = g_tb_v[a] + (c + 41)/42;
    }
  }
}

__global__ void k_scatter(int N){
  __shared__ int sc[NAB], sb[NAB];
  if (threadIdx.x < NAB) sc[threadIdx.x] = 0;
  __syncthreads();
  int n = blockIdx.x*blockDim.x + threadIdx.x;
  int a = 0, p = 0;
  bool valid = (n < N);
  if (valid){ a = g_zn[n]; p = atomicAdd(&sc[a], 1); }
  __syncthreads();
  if (threadIdx.x < NAB) sb[threadIdx.x] = atomicAdd(&g_cursor[threadIdx.x], sc[threadIdx.x]);
  __syncthreads();
  if (valid) g_perm[sb[a] + p] = n;
}

// ---------- main kernel helpers ----------
__device__ __forceinline__ void meta(int t, int ts_tot,
    int& isv, int& base, int& end, int& key, int& width){
  isv = (t >= ts_tot) ? 1 : 0;
  int tt = isv ? t - ts_tot : t;
  const int* tb = isv ? g_tb_v : g_tb_s;
  int a = 0;
  while (tt >= tb[a+1]) ++a;
  int tile = tt - tb[a];
  width = isv ? 42 : 128;
  base = g_off[a] + tile*width;
  end  = g_off[a+1];
  key  = (isv ? NAB : 0) + a;
}

__device__ __forceinline__ void pf_ld(const float* __restrict__ src, int cb, int isv,
                                      const int* sn, int tid, float4 pv[4]){
  if (!isv){
    #pragma unroll
    for (int i=0;i<4;++i){
      int q = tid + i*512;
      int ln = q>>4, u=(q&15)<<2;
      int node = sn[ln];
      if (node>=0) pv[i] = *(const float4*)(src + (size_t)node*512 + cb + u);
    }
  } else {
    #pragma unroll
    for (int i=0;i<4;++i){
      int q = tid + i*512;
      if (q>=2016) break;
      int ln = q/48, u=(q-ln*48)<<2;
      int node = sn[ln];
      if (node>=0) pv[i] = *(const float4*)(src + (size_t)node*512 + cb + u);
    }
  }
}
__device__ __forceinline__ void pf_st(char* Ad, int isv, const int* sn, int tid,
                                      const float4 pv[4]){
  if (!isv){
    #pragma unroll
    for (int i=0;i<4;++i){
      int q = tid + i*512;
      int ln = q>>4, u=(q&15)<<2;
      if (sn[ln] < 0) continue;
      __half2* d = (__half2*)(Ad + ln*144 + u*2);
      d[0] = __floats2half2_rn(pv[i].x, pv[i].y);
      d[1] = __floats2half2_rn(pv[i].z, pv[i].w);
    }
  } else {
    #pragma unroll
    for (int i=0;i<4;++i){
      int q = tid + i*512;
      if (q>=2016) break;
      int ln = q/48, u=(q-ln*48)<<2;
      if (sn[ln] < 0) continue;
      float vv[4] = {pv[i].x, pv[i].y, pv[i].z, pv[i].w};
      #pragma unroll
      for (int e=0;e<4;++e){
        int jr = u + e;
        int il = jr/3, x = jr - 3*il;
        *(__half*)(Ad + (3*ln + x)*144 + il*2) = __float2half_rn(vv[e]);
      }
    }
  }
}

// ---------- main kernel ----------
// SMEM: [0, 73728)             B weights: 4 chunks x [128 o][72 halves] (144B rows)
//       [73728, 73728+36864)   A double buffer: 2 x [128 m][72 halves]
//       [110592, 110592+67584) C stage [128][132] fp32
#define B_BYTES   73728
#define A_BYTES   18432
#define STAGE_OFF (B_BYTES + 2*A_BYTES)
#define SMEM_BYTES (STAGE_OFF + 128*132*4)

__global__ void __launch_bounds__(512) k_main(
    const float* __restrict__ Xm, const float* __restrict__ Xf,
    float* __restrict__ out){
  extern __shared__ char smem[];
  char*  Abuf  = smem + B_BYTES;
  float* stage = (float*)(smem + STAGE_OFF);
  __shared__ int snode[2][128];
  __shared__ int s_grab;

  const int tid  = threadIdx.x;
  const int lane = tid & 31;
  const int wid  = tid >> 5;
  const int wm = wid & 3, wn = wid >> 2;   // 4x4 warps, each 32 rows x 32 cols
  const int g4 = lane >> 2, t4 = lane & 3;
  const unsigned smb = su32(smem);
  const unsigned Ab  = smb + B_BYTES;

  const int ra  = lane & 15;
  const int ca  = (lane >> 4) << 3;
  const int rb  = ((lane >> 4) & 1)*8 + (lane & 7);
  const int cb2 = ((lane >> 3) & 1) << 3;

  const int ts_tot = g_tb_s[NAB];
  const int tv_tot = g_tb_v[NAB];
  const int total  = ts_tot + tv_tot;

  if (tid == 0) s_grab = atomicAdd(&g_work, CHUNK);
  __syncthreads();
  int rs = s_grab;
  int re = rs + CHUNK; if (re > total) re = total;
  int t = rs;
  int cur = -1, sp = 0;
  bool havePre = false;

  while (t < total){
    int isv, base, end, key, width;
    meta(t, ts_tot, isv, base, end, key, width);
    if (t == re-1 && tid == 0) s_grab = atomicAdd(&g_work, CHUNK);
    if (!havePre && tid < width)
      snode[sp][tid] = (base + tid < end) ? g_perm[base + tid] : -1;
    if (key != cur){
      cur = key;
      const float4* srcW = (const float4*)(g_Wh + (size_t)key*36864);
      float4* dstW = (float4*)smem;
      #pragma unroll 3
      for (int q = tid; q < 4608; q += 512) dstW[q] = srcW[q];
    }
    __syncthreads();   // B0: B, snode, s_grab visible; prev tile fully done

    if (!havePre){     // cold start of this CTA: gather chunk 0 now
      float4 pv0[4];
      pf_ld(Xm, isv ? 128 : 0, isv, snode[sp], tid, pv0);
      pf_st(Abuf, isv, snode[sp], tid, pv0);
      __syncthreads();
    }

    int nt = (t+1 < re) ? t+1 : s_grab;
    const bool hasN = (nt < total);
    int nisv=0, nbase=0, nend=0, nkey=0, nwidth=0;
    if (hasN) meta(nt, ts_tot, nisv, nbase, nend, nkey, nwidth);

    float acc[2][4][4];
    #pragma unroll
    for (int i=0;i<2;++i)
      #pragma unroll
      for (int j=0;j<4;++j)
        #pragma unroll
        for (int e=0;e<4;++e) acc[i][j][e] = 0.f;

    for (int kc = 0; kc < 4; ++kc){
      if (kc > 0) __syncthreads();   // STS of chunk kc visible; buf (kc+1)&1 free

      // ---- prefetch (chunk kc+1 of this tile, or chunk 0 of next tile) ----
      float4 pv[4];
      const bool doPre = (kc < 3) || hasN;
      const float* psrc; int pcb, pisv; const int* psn;
      if (kc < 3){
        int nk = kc + 1;
        psrc = (nk < 2) ? Xm : Xf;
        pisv = isv;
        pcb  = isv ? 128 + (nk & 1)*192 : (nk & 1)*64;
        psn  = snode[sp];
      } else {
        psrc = Xm; pisv = nisv; pcb = nisv ? 128 : 0; psn = snode[sp^1];
      }
      if (doPre) pf_ld(psrc, pcb, pisv, psn, tid, pv);

      if (kc == 2 && hasN && tid < nwidth)
        snode[sp^1][tid] = (nbase + tid < nend) ? g_perm[nbase + tid] : -1;

      // ---- MMA on chunk kc ----
      const unsigned Ac = Ab + (unsigned)((kc & 1)*A_BYTES);
      const unsigned Bk = smb + (unsigned)(kc*A_BYTES);
      #pragma unroll
      for (int ks = 0; ks < 4; ++ks){
        const int k0 = ks*16;
        unsigned af[2][4], bf[2][4];
        ldsm4(af[0], Ac + (unsigned)((wm*32      + ra)*144 + (k0+ca)*2));
        ldsm4(af[1], Ac + (unsigned)((wm*32 + 16 + ra)*144 + (k0+ca)*2));
        ldsm4(bf[0], Bk + (unsigned)((wn*32      + rb)*144 + (k0+cb2)*2));
        ldsm4(bf[1], Bk + (unsigned)((wn*32 + 16 + rb)*144 + (k0+cb2)*2));
        #pragma unroll
        for (int mi = 0; mi < 2; ++mi){
          hmma(acc[mi][0], af[mi], bf[0][0], bf[0][1]);
          hmma(acc[mi][1], af[mi], bf[0][2], bf[0][3]);
          hmma(acc[mi][2], af[mi], bf[1][0], bf[1][1]);
          hmma(acc[mi][3], af[mi], bf[1][2], bf[1][3]);
        }
      }

      // ---- convert + STS prefetched chunk into the other buffer ----
      if (doPre)
        pf_st(Abuf + ((kc+1) & 1)*A_BYTES, pisv, psn, tid, pv);
    }
    __syncthreads();  // B4: last MMA + STS0' done

    // ---- epilogue: regs -> stage (full 128x128) ----
    #pragma unroll
    for (int mi = 0; mi < 2; ++mi){
      int r = wm*32 + mi*16 + g4;
      #pragma unroll
      for (int jj = 0; jj < 4; ++jj){
        int c = wn*32 + jj*8 + 2*t4;
        float* d1 = stage + r*132 + c;
        d1[0] = acc[mi][jj][0]; d1[1] = acc[mi][jj][1];
        float* d2 = stage + (r+8)*132 + c;
        d2[0] = acc[mi][jj][2]; d2[1] = acc[mi][jj][3];
      }
    }
    __syncthreads();  // B5

    // ---- stage -> global ----
    if (!isv){
      #pragma unroll
      for (int i = 0; i < 8; ++i){
        int q = tid + i*512;
        int ln = q >> 5, u = (q & 31) << 2;
        int node = snode[sp][ln];
        if (node < 0) continue;
        float4 v = *(float4*)(stage + ln*132 + u);
        *(float4*)(out + (size_t)node*512 + u) = v;
      }
    } else {
      #pragma unroll
      for (int i = 0; i < 8; ++i){
        int q = tid + i*512;
        if (q >= 4032) break;
        int ln = q / 96, u = (q - ln*96) << 2;
        int node = snode[sp][ln];
        if (node < 0) continue;
        float4 v;
        float* vp = (float*)&v;
        #pragma unroll
        for (int e=0;e<4;++e){
          int jr = u + e;
          int ol = jr/3, x = jr - 3*ol;
          vp[e] = stage[(3*ln + x)*132 + ol];
        }
        *(float4*)(out + (size_t)node*512 + 128 + u) = v;
      }
    }

    // ---- advance ----
    havePre = hasN;
    sp ^= 1;
    if (t+1 < re){ t = t+1; }
    else { rs = nt; re = rs + CHUNK; if (re > total) re = total; t = nt; }
  }
}

extern "C" void kernel_launch(void* const* d_in, const int* in_sizes, int n_in,
                              void* d_out, int out_size){
  const float* m_i   = (const float*)d_in[0];
  const float* nfeat = (const float*)d_in[1];
  const float* attrs = (const float*)d_in[2];
  const float* Wl0   = (const float*)d_in[3];
  const float* Wl1   = (const float*)d_in[4];
  const float* Wt0   = (const float*)d_in[5];
  const float* Wt1   = (const float*)d_in[6];
  float* out = (float*)d_out;
  int N = in_sizes[0] / 512;
  if (N > MAXN) return;

  cudaFuncSetAttribute(k_main, cudaFuncAttributeMaxDynamicSharedMemorySize, SMEM_BYTES);

  k_prepw<<<(20*32768 + 255)/256, 256>>>(Wl0, Wl1, Wt0, Wt1);
  k_zero<<<1, 32>>>();
  k_hist<<<(N + 255)/256, 256>>>(attrs, N);
  k_scan<<<1, 1>>>();
  k_scatter<<<(N + 255)/256, 256>>>(N);
  k_main<<<148, 512, SMEM_BYTES>>>(m_i, nfeat, out);
}